// round 3
// baseline (speedup 1.0000x reference)
#include <cuda_runtime.h>
#include <cuda_bf16.h>
#include <math.h>

// Problem constants
#define B_   32
#define C_   256
#define H_   64
#define W_   64
#define MIP_ 8
#define OUP_ 256

// Scratch (device globals — no allocation allowed)
__device__ __align__(16) float g_a [B_ * C_ * (H_ + W_)];   // 4 MiB  (a_h | a_w per plane)
__device__ __align__(16) float g_gh[B_ * OUP_ * H_];        // 2 MiB
__device__ __align__(16) float g_gw[B_ * OUP_ * W_];        // 2 MiB

// ---------------------------------------------------------------------------
// K1: per-(b,c) plane stats -> a[plane][0..127]
//   a_h[h] = (rowsum[h] + softmax_h(rowmax)[h]) / 64
//   a_w[w] = (colsum[w] + softmax_w(colmax)[w]) / 64
// ---------------------------------------------------------------------------
__global__ __launch_bounds__(256) void k1_stats(const float* __restrict__ x)
{
    __shared__ float sh[64 * 65];            // padded rows: 2-way max conflicts
    __shared__ float rmax[64], rsum[64], cmax[64], csum[64];

    const int tid = threadIdx.x;
    const long plane = blockIdx.x;           // 0 .. B*C-1
    const float4* xp = reinterpret_cast<const float4*>(x) + plane * 1024;

    // Stage the 64x64 tile into smem
    #pragma unroll
    for (int i = 0; i < 4; i++) {
        int idx = i * 256 + tid;             // float4 index 0..1023
        float4 v = xp[idx];
        int r  = idx >> 4;
        int c4 = (idx & 15) << 2;
        float* d = &sh[r * 65 + c4];
        d[0] = v.x; d[1] = v.y; d[2] = v.z; d[3] = v.w;
    }
    __syncthreads();

    const int r   = tid >> 2;                // row or col index (0..63)
    const int seg = tid & 3;                 // 16-element segment

    // Row reductions (max over w, sum over w)
    {
        const float* rp = &sh[r * 65 + seg * 16];
        float mx = rp[0], sm = rp[0];
        #pragma unroll
        for (int j = 1; j < 16; j++) { float v = rp[j]; mx = fmaxf(mx, v); sm += v; }
        mx = fmaxf(mx, __shfl_xor_sync(0xFFFFFFFFu, mx, 1));
        mx = fmaxf(mx, __shfl_xor_sync(0xFFFFFFFFu, mx, 2));
        sm += __shfl_xor_sync(0xFFFFFFFFu, sm, 1);
        sm += __shfl_xor_sync(0xFFFFFFFFu, sm, 2);
        if (seg == 0) { rmax[r] = mx; rsum[r] = sm; }
    }
    // Column reductions (max over h, sum over h)
    {
        float mx = -1e30f, sm = 0.f;
        #pragma unroll
        for (int j = 0; j < 16; j++) {
            float v = sh[(seg * 16 + j) * 65 + r];
            mx = fmaxf(mx, v); sm += v;
        }
        mx = fmaxf(mx, __shfl_xor_sync(0xFFFFFFFFu, mx, 1));
        mx = fmaxf(mx, __shfl_xor_sync(0xFFFFFFFFu, mx, 2));
        sm += __shfl_xor_sync(0xFFFFFFFFu, sm, 1);
        sm += __shfl_xor_sync(0xFFFFFFFFu, sm, 2);
        if (seg == 0) { cmax[r] = mx; csum[r] = sm; }
    }
    __syncthreads();

    // Softmax + emit: warp 0 -> rows (a_h), warp 1 -> cols (a_w)
    const int w    = tid >> 5;
    const int lane = tid & 31;
    if (w < 2) {
        const float* ma = (w == 0) ? rmax : cmax;
        const float* sa = (w == 0) ? rsum : csum;
        float v0 = ma[lane], v1 = ma[lane + 32];
        float m = fmaxf(v0, v1);
        #pragma unroll
        for (int o = 16; o > 0; o >>= 1) m = fmaxf(m, __shfl_xor_sync(0xFFFFFFFFu, m, o));
        float e0 = __expf(v0 - m), e1 = __expf(v1 - m);
        float s = e0 + e1;
        #pragma unroll
        for (int o = 16; o > 0; o >>= 1) s += __shfl_xor_sync(0xFFFFFFFFu, s, o);
        float inv = 1.f / s;
        float* ob = g_a + plane * 128 + w * 64;
        ob[lane]      = (sa[lane]      + e0 * inv) * 0.015625f;   // /64
        ob[lane + 32] = (sa[lane + 32] + e1 * inv) * 0.015625f;
    }
}

// ---------------------------------------------------------------------------
// K2: per batch — y = w1 @ a (8x128), BN+hswish, then
//     g_h = sigmoid(wh @ y_h), g_w = sigmoid(ww @ y_w)
// ---------------------------------------------------------------------------
__global__ __launch_bounds__(128) void k2_gate(const float* __restrict__ w1,
                                               const float* __restrict__ gamma,
                                               const float* __restrict__ beta,
                                               const float* __restrict__ mean,
                                               const float* __restrict__ var,
                                               const float* __restrict__ wh,
                                               const float* __restrict__ ww)
{
    __shared__ float w1s[MIP_ * C_];          // 8 KB
    __shared__ float ysm[MIP_][128];

    const int tid = threadIdx.x;              // 0..127 == s index
    const int b   = blockIdx.x;

    for (int i = tid; i < MIP_ * C_; i += 128) w1s[i] = w1[i];
    __syncthreads();

    const float* ab = g_a + (long)b * (C_ * 128);
    float acc[MIP_];
    #pragma unroll
    for (int m = 0; m < MIP_; m++) acc[m] = 0.f;

    for (int c = 0; c < C_; c++) {
        float av = ab[c * 128 + tid];
        #pragma unroll
        for (int m = 0; m < MIP_; m++) acc[m] = fmaf(w1s[m * C_ + c], av, acc[m]);
    }
    #pragma unroll
    for (int m = 0; m < MIP_; m++) {
        float sc = gamma[m] * rsqrtf(var[m] + 1e-5f);
        float sf = beta[m] - mean[m] * sc;
        float v  = fmaf(acc[m], sc, sf);
        ysm[m][tid] = v * fminf(fmaxf(v + 3.f, 0.f), 6.f) * (1.f / 6.f);  // hswish
    }
    __syncthreads();

    // Each thread handles two output channels o
    #pragma unroll
    for (int oo = 0; oo < 2; oo++) {
        int o = tid + oo * 128;
        float whr[MIP_], wwr[MIP_];
        #pragma unroll
        for (int m = 0; m < MIP_; m++) { whr[m] = wh[o * MIP_ + m]; wwr[m] = ww[o * MIP_ + m]; }
        float* ghp = g_gh + ((long)b * OUP_ + o) * 64;
        float* gwp = g_gw + ((long)b * OUP_ + o) * 64;
        for (int h = 0; h < 64; h++) {
            float ah = 0.f, aw = 0.f;
            #pragma unroll
            for (int m = 0; m < MIP_; m++) {
                ah = fmaf(whr[m], ysm[m][h],      ah);
                aw = fmaf(wwr[m], ysm[m][64 + h], aw);
            }
            ghp[h] = 1.f / (1.f + __expf(-ah));
            gwp[h] = 1.f / (1.f + __expf(-aw));
        }
    }
}

// ---------------------------------------------------------------------------
// K3: out = x * g_h[b,c,h] * g_w[b,c,w]  (float4 streaming)
// Blocks run in reverse order so the x-tail left in L2 by K1 is reused.
// ---------------------------------------------------------------------------
__global__ __launch_bounds__(256) void k3_apply(const float* __restrict__ x,
                                                float* __restrict__ out)
{
    const int  bid  = gridDim.x - 1 - blockIdx.x;      // reverse for L2 reuse
    const long idx4 = (long)bid * 256 + threadIdx.x;   // float4 index

    float4 xv = reinterpret_cast<const float4*>(x)[idx4];
    int row = (int)(idx4 >> 4);      // (b*256+c)*64 + h
    int w4  = (int)(idx4 & 15);
    int bc  = row >> 6;
    int h   = row & 63;

    float  ghv = g_gh[bc * 64 + h];
    float4 gwv = reinterpret_cast<const float4*>(g_gw)[(bc << 4) + w4];

    float4 ov;
    ov.x = xv.x * ghv * gwv.x;
    ov.y = xv.y * ghv * gwv.y;
    ov.z = xv.z * ghv * gwv.z;
    ov.w = xv.w * ghv * gwv.w;
    reinterpret_cast<float4*>(out)[idx4] = ov;
}

// ---------------------------------------------------------------------------
extern "C" void kernel_launch(void* const* d_in, const int* in_sizes, int n_in,
                              void* d_out, int out_size)
{
    const float* x     = (const float*)d_in[0];
    const float* w1    = (const float*)d_in[1];
    const float* gamma = (const float*)d_in[2];
    const float* beta  = (const float*)d_in[3];
    const float* mean  = (const float*)d_in[4];
    const float* var   = (const float*)d_in[5];
    const float* wh    = (const float*)d_in[6];
    const float* ww    = (const float*)d_in[7];
    float* out = (float*)d_out;

    k1_stats<<<B_ * C_, 256>>>(x);
    k2_gate <<<B_,       128>>>(w1, gamma, beta, mean, var, wh, ww);
    k3_apply<<<(B_ * C_ * H_ * W_) / (4 * 256), 256>>>(x, out);
}

// round 4
// speedup vs baseline: 1.7630x; 1.7630x over previous
#include <cuda_runtime.h>
#include <cuda_bf16.h>
#include <math.h>

// Problem constants
#define B_   32
#define C_   256
#define H_   64
#define W_   64
#define MIP_ 8
#define OUP_ 256

// Scratch (device globals — no allocation allowed)
__device__ __align__(16) float g_a [B_ * C_ * (H_ + W_)];   // 4 MiB  (a_h | a_w per plane)
__device__ __align__(16) float g_y [B_ * MIP_ * 128];       // y after BN+hswish
__device__ __align__(16) float g_gh[B_ * OUP_ * H_];        // 2 MiB
__device__ __align__(16) float g_gw[B_ * OUP_ * W_];        // 2 MiB

// ---------------------------------------------------------------------------
// K1: per-(b,c) plane stats -> a[plane][0..127]
//   a_h[h] = (rowsum[h] + softmax_h(rowmax)[h]) / 64
//   a_w[w] = (colsum[w] + softmax_w(colmax)[w]) / 64
// Register-resident: rows reduced via shfl (each 16-lane group = one full row),
// columns via per-thread 4-column partials + one padded smem store.
// ---------------------------------------------------------------------------
__global__ __launch_bounds__(256) void k1_stats(const float* __restrict__ x)
{
    __shared__ float rmax[64], rsum[64], cmax[64], csum[64];
    __shared__ float pmax[16][68], psum[16][68];   // pitch 68: conflict-free f4 stores

    const int tid = threadIdx.x;
    const long plane = blockIdx.x;                 // 0 .. B*C-1
    const float4* xp = reinterpret_cast<const float4*>(x) + plane * 1024;

    float4 v[4];
    #pragma unroll
    for (int i = 0; i < 4; i++) v[i] = xp[i * 256 + tid];

    // Row reductions: 16 consecutive lanes cover one full row per i
    #pragma unroll
    for (int i = 0; i < 4; i++) {
        float mx = fmaxf(fmaxf(v[i].x, v[i].y), fmaxf(v[i].z, v[i].w));
        float sm = (v[i].x + v[i].y) + (v[i].z + v[i].w);
        #pragma unroll
        for (int o = 1; o < 16; o <<= 1) {
            mx = fmaxf(mx, __shfl_xor_sync(0xFFFFFFFFu, mx, o));
            sm += __shfl_xor_sync(0xFFFFFFFFu, sm, o);
        }
        if ((tid & 15) == 0) {
            int r = i * 16 + (tid >> 4);
            rmax[r] = mx; rsum[r] = sm;
        }
    }

    // Column partials: this thread owns cols 4k..4k+3 (k = tid&15) over 4 rows
    float cm0 = v[0].x, cm1 = v[0].y, cm2 = v[0].z, cm3 = v[0].w;
    float cs0 = v[0].x, cs1 = v[0].y, cs2 = v[0].z, cs3 = v[0].w;
    #pragma unroll
    for (int i = 1; i < 4; i++) {
        cm0 = fmaxf(cm0, v[i].x); cs0 += v[i].x;
        cm1 = fmaxf(cm1, v[i].y); cs1 += v[i].y;
        cm2 = fmaxf(cm2, v[i].z); cs2 += v[i].z;
        cm3 = fmaxf(cm3, v[i].w); cs3 += v[i].w;
    }
    {
        int g = tid >> 4, k = tid & 15;
        *reinterpret_cast<float4*>(&pmax[g][k * 4]) = make_float4(cm0, cm1, cm2, cm3);
        *reinterpret_cast<float4*>(&psum[g][k * 4]) = make_float4(cs0, cs1, cs2, cs3);
    }
    __syncthreads();

    if (tid < 64) {
        float m = pmax[0][tid], s = psum[0][tid];
        #pragma unroll
        for (int g = 1; g < 16; g++) { m = fmaxf(m, pmax[g][tid]); s += psum[g][tid]; }
        cmax[tid] = m; csum[tid] = s;
    }
    __syncthreads();

    // Softmax + emit: warp 0 -> rows (a_h), warp 1 -> cols (a_w)
    const int w    = tid >> 5;
    const int lane = tid & 31;
    if (w < 2) {
        const float* ma = (w == 0) ? rmax : cmax;
        const float* sa = (w == 0) ? rsum : csum;
        float v0 = ma[lane], v1 = ma[lane + 32];
        float m = fmaxf(v0, v1);
        #pragma unroll
        for (int o = 16; o > 0; o >>= 1) m = fmaxf(m, __shfl_xor_sync(0xFFFFFFFFu, m, o));
        float e0 = __expf(v0 - m), e1 = __expf(v1 - m);
        float s = e0 + e1;
        #pragma unroll
        for (int o = 16; o > 0; o >>= 1) s += __shfl_xor_sync(0xFFFFFFFFu, s, o);
        float inv = 1.f / s;
        float* ob = g_a + plane * 128 + w * 64;
        ob[lane]      = (sa[lane]      + e0 * inv) * 0.015625f;   // /64
        ob[lane + 32] = (sa[lane + 32] + e1 * inv) * 0.015625f;
    }
}

// ---------------------------------------------------------------------------
// K2a: per batch — y = hswish(BN(w1 @ a))  (8x128 per batch) -> g_y
// ---------------------------------------------------------------------------
__global__ __launch_bounds__(128) void k2a_y(const float* __restrict__ w1,
                                             const float* __restrict__ gamma,
                                             const float* __restrict__ beta,
                                             const float* __restrict__ mean,
                                             const float* __restrict__ var)
{
    __shared__ float w1s[MIP_ * C_];          // 8 KB

    const int tid = threadIdx.x;              // 0..127 == s index
    const int b   = blockIdx.x;

    for (int i = tid; i < MIP_ * C_; i += 128) w1s[i] = w1[i];
    __syncthreads();

    const float* ab = g_a + (long)b * (C_ * 128);
    float acc[MIP_];
    #pragma unroll
    for (int m = 0; m < MIP_; m++) acc[m] = 0.f;

    #pragma unroll 4
    for (int c = 0; c < C_; c++) {
        float av = ab[c * 128 + tid];
        #pragma unroll
        for (int m = 0; m < MIP_; m++) acc[m] = fmaf(w1s[m * C_ + c], av, acc[m]);
    }
    #pragma unroll
    for (int m = 0; m < MIP_; m++) {
        float sc = gamma[m] * rsqrtf(var[m] + 1e-5f);
        float sf = beta[m] - mean[m] * sc;
        float v  = fmaf(acc[m], sc, sf);
        g_y[(b * MIP_ + m) * 128 + tid] =
            v * fminf(fmaxf(v + 3.f, 0.f), 6.f) * (1.f / 6.f);    // hswish
    }
}

// ---------------------------------------------------------------------------
// K2b: gates. grid = B_*16 blocks x 256 threads.
// Thread -> (b, o, kind in {gh,gw}, 8-wide h segment): 8 outputs each.
// ---------------------------------------------------------------------------
__global__ __launch_bounds__(256) void k2b_gate(const float* __restrict__ wh,
                                                const float* __restrict__ ww)
{
    __shared__ float ys[MIP_ * 128];          // y for this batch (4 KB)

    const int tid = threadIdx.x;
    const int b   = blockIdx.x >> 4;          // 16 blocks per batch

    for (int i = tid; i < MIP_ * 128; i += 256) ys[i] = g_y[b * (MIP_ * 128) + i];
    __syncthreads();

    const int gidx = blockIdx.x * 256 + tid;
    const int bo   = gidx >> 4;               // b*256 + o
    const int o    = bo & 255;
    const int kind = (gidx >> 3) & 1;         // 0 -> gh, 1 -> gw
    const int seg  = gidx & 7;                // h chunk of 8
    const int base = kind * 64 + seg * 8;

    const float* wrow = (kind ? ww : wh) + o * MIP_;
    float wr[MIP_];
    #pragma unroll
    for (int m = 0; m < MIP_; m++) wr[m] = wrow[m];

    float acc[8];
    #pragma unroll
    for (int j = 0; j < 8; j++) acc[j] = 0.f;

    #pragma unroll
    for (int m = 0; m < MIP_; m++) {
        float4 y0 = *reinterpret_cast<const float4*>(&ys[m * 128 + base]);
        float4 y1 = *reinterpret_cast<const float4*>(&ys[m * 128 + base + 4]);
        acc[0] = fmaf(wr[m], y0.x, acc[0]);
        acc[1] = fmaf(wr[m], y0.y, acc[1]);
        acc[2] = fmaf(wr[m], y0.z, acc[2]);
        acc[3] = fmaf(wr[m], y0.w, acc[3]);
        acc[4] = fmaf(wr[m], y1.x, acc[4]);
        acc[5] = fmaf(wr[m], y1.y, acc[5]);
        acc[6] = fmaf(wr[m], y1.z, acc[6]);
        acc[7] = fmaf(wr[m], y1.w, acc[7]);
    }

    float r[8];
    #pragma unroll
    for (int j = 0; j < 8; j++) r[j] = 1.f / (1.f + __expf(-acc[j]));

    float* outp = (kind ? g_gw : g_gh) + bo * 64 + seg * 8;
    *reinterpret_cast<float4*>(outp)     = make_float4(r[0], r[1], r[2], r[3]);
    *reinterpret_cast<float4*>(outp + 4) = make_float4(r[4], r[5], r[6], r[7]);
}

// ---------------------------------------------------------------------------
// K3: out = x * g_h[bc,h] * g_w[bc,w]. One block == one (b,c) plane (4 KB x4).
// 4 front-batched streaming loads per thread; gw hoisted (constant over k).
// Reverse block order reuses the x tail K1 left in L2.
// ---------------------------------------------------------------------------
__global__ __launch_bounds__(256) void k3_apply(const float* __restrict__ x,
                                                float* __restrict__ out)
{
    const int  bc   = gridDim.x - 1 - blockIdx.x;       // plane index
    const int  tid  = threadIdx.x;
    const long base = (long)bc * 1024 + tid;            // float4 index

    const float4* xp = reinterpret_cast<const float4*>(x);
    float4*       op = reinterpret_cast<float4*>(out);

    float4 xv[4];
    #pragma unroll
    for (int k = 0; k < 4; k++) xv[k] = __ldcs(xp + base + k * 256);

    const float4 gwv = *(reinterpret_cast<const float4*>(g_gw) + bc * 16 + (tid & 15));
    const float* ghp = g_gh + bc * 64;

    #pragma unroll
    for (int k = 0; k < 4; k++) {
        float ghv = ghp[k * 16 + (tid >> 4)];
        float4 ov;
        ov.x = xv[k].x * ghv * gwv.x;
        ov.y = xv[k].y * ghv * gwv.y;
        ov.z = xv[k].z * ghv * gwv.z;
        ov.w = xv[k].w * ghv * gwv.w;
        __stcs(op + base + k * 256, ov);
    }
}

// ---------------------------------------------------------------------------
extern "C" void kernel_launch(void* const* d_in, const int* in_sizes, int n_in,
                              void* d_out, int out_size)
{
    const float* x     = (const float*)d_in[0];
    const float* w1    = (const float*)d_in[1];
    const float* gamma = (const float*)d_in[2];
    const float* beta  = (const float*)d_in[3];
    const float* mean  = (const float*)d_in[4];
    const float* var   = (const float*)d_in[5];
    const float* wh    = (const float*)d_in[6];
    const float* ww    = (const float*)d_in[7];
    float* out = (float*)d_out;

    k1_stats<<<B_ * C_, 256>>>(x);
    k2a_y   <<<B_,       128>>>(w1, gamma, beta, mean, var);
    k2b_gate<<<B_ * 16,  256>>>(wh, ww);
    k3_apply<<<B_ * C_,  256>>>(x, out);
}

// round 5
// speedup vs baseline: 2.1413x; 1.2146x over previous
#include <cuda_runtime.h>
#include <cuda_bf16.h>
#include <math.h>

// Problem constants
#define B_   32
#define C_   256
#define H_   64
#define W_   64
#define MIP_ 8
#define OUP_ 256

// Scratch (device globals — no allocation allowed)
__device__ __align__(16) float g_a [B_ * C_ * (H_ + W_)];   // 4 MiB  (a_h | a_w per plane)
__device__ __align__(16) float g_gh[B_ * OUP_ * H_];        // 2 MiB
__device__ __align__(16) float g_gw[B_ * OUP_ * W_];        // 2 MiB

// ---------------------------------------------------------------------------
// K1: per-(b,c) plane stats -> a[plane][0..127]
//   a_h[h] = (rowsum[h] + softmax_h(rowmax)[h]) / 64
//   a_w[w] = (colsum[w] + softmax_w(colmax)[w]) / 64
// ---------------------------------------------------------------------------
__global__ __launch_bounds__(256) void k1_stats(const float* __restrict__ x)
{
    __shared__ float rmax[64], rsum[64], cmax[64], csum[64];
    __shared__ float pmax[16][68], psum[16][68];   // pitch 68: conflict-free f4 stores

    const int tid = threadIdx.x;
    const long plane = blockIdx.x;                 // 0 .. B*C-1
    const float4* xp = reinterpret_cast<const float4*>(x) + plane * 1024;

    float4 v[4];
    #pragma unroll
    for (int i = 0; i < 4; i++) v[i] = xp[i * 256 + tid];

    // Row reductions: 16 consecutive lanes cover one full row per i
    #pragma unroll
    for (int i = 0; i < 4; i++) {
        float mx = fmaxf(fmaxf(v[i].x, v[i].y), fmaxf(v[i].z, v[i].w));
        float sm = (v[i].x + v[i].y) + (v[i].z + v[i].w);
        #pragma unroll
        for (int o = 1; o < 16; o <<= 1) {
            mx = fmaxf(mx, __shfl_xor_sync(0xFFFFFFFFu, mx, o));
            sm += __shfl_xor_sync(0xFFFFFFFFu, sm, o);
        }
        if ((tid & 15) == 0) {
            int r = i * 16 + (tid >> 4);
            rmax[r] = mx; rsum[r] = sm;
        }
    }

    // Column partials: this thread owns cols 4k..4k+3 (k = tid&15) over 4 rows
    float cm0 = v[0].x, cm1 = v[0].y, cm2 = v[0].z, cm3 = v[0].w;
    float cs0 = v[0].x, cs1 = v[0].y, cs2 = v[0].z, cs3 = v[0].w;
    #pragma unroll
    for (int i = 1; i < 4; i++) {
        cm0 = fmaxf(cm0, v[i].x); cs0 += v[i].x;
        cm1 = fmaxf(cm1, v[i].y); cs1 += v[i].y;
        cm2 = fmaxf(cm2, v[i].z); cs2 += v[i].z;
        cm3 = fmaxf(cm3, v[i].w); cs3 += v[i].w;
    }
    {
        int g = tid >> 4, k = tid & 15;
        *reinterpret_cast<float4*>(&pmax[g][k * 4]) = make_float4(cm0, cm1, cm2, cm3);
        *reinterpret_cast<float4*>(&psum[g][k * 4]) = make_float4(cs0, cs1, cs2, cs3);
    }
    __syncthreads();

    if (tid < 64) {
        float m = pmax[0][tid], s = psum[0][tid];
        #pragma unroll
        for (int g = 1; g < 16; g++) { m = fmaxf(m, pmax[g][tid]); s += psum[g][tid]; }
        cmax[tid] = m; csum[tid] = s;
    }
    __syncthreads();

    // Softmax + emit: warp 0 -> rows (a_h), warp 1 -> cols (a_w)
    const int w    = tid >> 5;
    const int lane = tid & 31;
    if (w < 2) {
        const float* ma = (w == 0) ? rmax : cmax;
        const float* sa = (w == 0) ? rsum : csum;
        float v0 = ma[lane], v1 = ma[lane + 32];
        float m = fmaxf(v0, v1);
        #pragma unroll
        for (int o = 16; o > 0; o >>= 1) m = fmaxf(m, __shfl_xor_sync(0xFFFFFFFFu, m, o));
        float e0 = __expf(v0 - m), e1 = __expf(v1 - m);
        float s = e0 + e1;
        #pragma unroll
        for (int o = 16; o > 0; o >>= 1) s += __shfl_xor_sync(0xFFFFFFFFu, s, o);
        float inv = 1.f / s;
        float* ob = g_a + plane * 128 + w * 64;
        ob[lane]      = (sa[lane]      + e0 * inv) * 0.015625f;   // /64
        ob[lane + 32] = (sa[lane + 32] + e1 * inv) * 0.015625f;
    }
}

// ---------------------------------------------------------------------------
// K2 (fused): per batch b —
//   phase1: partial y_pre = w1 @ a  (8 warps, warp = 32-c slice, lane = s/4, MLP~8)
//   phase2: reduce partials + BN + hswish -> yt[s][m] (transposed, pitch 12)
//   phase3: gh = sigmoid(wh@y_h), gw = sigmoid(ww@y_w)  (512 threads)
// grid = B_ blocks x 512 threads.
// ---------------------------------------------------------------------------
__global__ __launch_bounds__(512) void k2_fused(const float* __restrict__ w1,
                                                const float* __restrict__ gamma,
                                                const float* __restrict__ beta,
                                                const float* __restrict__ mean,
                                                const float* __restrict__ var,
                                                const float* __restrict__ wh,
                                                const float* __restrict__ ww)
{
    __shared__ float w1s[MIP_ * C_];       // 8 KB
    __shared__ float part[8 * 32 * 33];    // [cgrp][lane(s4)][33]  ~33 KB, pitch 33
    __shared__ float yt[128 * 12];         // yt[s*12 + m]  (pitch 12, f4-aligned)

    const int tid = threadIdx.x;
    const int b   = blockIdx.x;

    for (int i = tid; i < MIP_ * C_; i += 512) w1s[i] = w1[i];
    __syncthreads();

    // -------- phase 1: warps 0..7 each own 32 c's; lane = s4 (float4 of s)
    if (tid < 256) {
        const int wrp  = tid >> 5;         // cgrp 0..7
        const int lane = tid & 31;         // s4 0..31
        const float4* ap = reinterpret_cast<const float4*>(g_a) +
                           ((long)b * C_ + wrp * 32) * 32 + lane;

        float acc[MIP_][4];
        #pragma unroll
        for (int m = 0; m < MIP_; m++)
            #pragma unroll
            for (int j = 0; j < 4; j++) acc[m][j] = 0.f;

        #pragma unroll 4
        for (int k = 0; k < 32; k++) {
            float4 av = ap[k * 32];                     // a[b][c][s4*4..]
            const float* wc = &w1s[wrp * 32 + k];       // w1[m][c], broadcast
            #pragma unroll
            for (int m = 0; m < MIP_; m++) {
                float wv = wc[m * C_];
                acc[m][0] = fmaf(wv, av.x, acc[m][0]);
                acc[m][1] = fmaf(wv, av.y, acc[m][1]);
                acc[m][2] = fmaf(wv, av.z, acc[m][2]);
                acc[m][3] = fmaf(wv, av.w, acc[m][3]);
            }
        }
        float* pb = &part[(wrp * 32 + lane) * 33];
        #pragma unroll
        for (int m = 0; m < MIP_; m++)
            #pragma unroll
            for (int j = 0; j < 4; j++) pb[m * 4 + j] = acc[m][j];
    }
    __syncthreads();

    // -------- phase 2: reduce 8 c-groups, BN + hswish, transpose into yt
    if (tid < 256) {
        const int m  = tid >> 5;
        const int s4 = tid & 31;
        const float sc = gamma[m] * rsqrtf(var[m] + 1e-5f);
        const float sf = beta[m] - mean[m] * sc;
        #pragma unroll
        for (int j = 0; j < 4; j++) {
            float s = 0.f;
            #pragma unroll
            for (int g = 0; g < 8; g++) s += part[(g * 32 + s4) * 33 + m * 4 + j];
            float v = fmaf(s, sc, sf);
            yt[(s4 * 4 + j) * 12 + m] =
                v * fminf(fmaxf(v + 3.f, 0.f), 6.f) * (1.f / 6.f);   // hswish
        }
    }
    __syncthreads();

    // -------- phase 3: gates. thread = (half = tid>>8, o = tid&255)
    {
        const int o    = tid & 255;
        const int half = tid >> 8;          // h range: half*32 .. +31
        const float4 wh0 = reinterpret_cast<const float4*>(wh)[o * 2];
        const float4 wh1 = reinterpret_cast<const float4*>(wh)[o * 2 + 1];
        const float4 ww0 = reinterpret_cast<const float4*>(ww)[o * 2];
        const float4 ww1 = reinterpret_cast<const float4*>(ww)[o * 2 + 1];

        float* ghp = g_gh + ((long)b * OUP_ + o) * 64;
        float* gwp = g_gw + ((long)b * OUP_ + o) * 64;

        #pragma unroll
        for (int chunk = 0; chunk < 2; chunk++) {
            const int hbase = half * 32 + chunk * 16;
            float rh[16], rw[16];
            #pragma unroll
            for (int hh = 0; hh < 16; hh++) {
                const int h = hbase + hh;
                float4 ya = *reinterpret_cast<const float4*>(&yt[h * 12]);
                float4 yb = *reinterpret_cast<const float4*>(&yt[h * 12 + 4]);
                float4 za = *reinterpret_cast<const float4*>(&yt[(64 + h) * 12]);
                float4 zb = *reinterpret_cast<const float4*>(&yt[(64 + h) * 12 + 4]);
                float ah = wh0.x*ya.x + wh0.y*ya.y + wh0.z*ya.z + wh0.w*ya.w
                         + wh1.x*yb.x + wh1.y*yb.y + wh1.z*yb.z + wh1.w*yb.w;
                float aw = ww0.x*za.x + ww0.y*za.y + ww0.z*za.z + ww0.w*za.w
                         + ww1.x*zb.x + ww1.y*zb.y + ww1.z*zb.z + ww1.w*zb.w;
                rh[hh] = __fdividef(1.f, 1.f + __expf(-ah));
                rw[hh] = __fdividef(1.f, 1.f + __expf(-aw));
            }
            #pragma unroll
            for (int q = 0; q < 4; q++) {
                *reinterpret_cast<float4*>(ghp + hbase + q * 4) =
                    make_float4(rh[q*4], rh[q*4+1], rh[q*4+2], rh[q*4+3]);
                *reinterpret_cast<float4*>(gwp + hbase + q * 4) =
                    make_float4(rw[q*4], rw[q*4+1], rw[q*4+2], rw[q*4+3]);
            }
        }
    }
}

// ---------------------------------------------------------------------------
// K3: out = x * g_h[bc,h] * g_w[bc,w]. One block == one (b,c) plane.
// 4 front-batched streaming loads per thread; gw hoisted (constant over k).
// Reverse block order reuses the x tail K1 left in L2.
// ---------------------------------------------------------------------------
__global__ __launch_bounds__(256) void k3_apply(const float* __restrict__ x,
                                                float* __restrict__ out)
{
    const int  bc   = gridDim.x - 1 - blockIdx.x;       // plane index
    const int  tid  = threadIdx.x;
    const long base = (long)bc * 1024 + tid;            // float4 index

    const float4* xp = reinterpret_cast<const float4*>(x);
    float4*       op = reinterpret_cast<float4*>(out);

    float4 xv[4];
    #pragma unroll
    for (int k = 0; k < 4; k++) xv[k] = __ldcs(xp + base + k * 256);

    const float4 gwv = *(reinterpret_cast<const float4*>(g_gw) + bc * 16 + (tid & 15));
    const float* ghp = g_gh + bc * 64;

    #pragma unroll
    for (int k = 0; k < 4; k++) {
        float ghv = ghp[k * 16 + (tid >> 4)];
        float4 ov;
        ov.x = xv[k].x * ghv * gwv.x;
        ov.y = xv[k].y * ghv * gwv.y;
        ov.z = xv[k].z * ghv * gwv.z;
        ov.w = xv[k].w * ghv * gwv.w;
        __stcs(op + base + k * 256, ov);
    }
}

// ---------------------------------------------------------------------------
extern "C" void kernel_launch(void* const* d_in, const int* in_sizes, int n_in,
                              void* d_out, int out_size)
{
    const float* x     = (const float*)d_in[0];
    const float* w1    = (const float*)d_in[1];
    const float* gamma = (const float*)d_in[2];
    const float* beta  = (const float*)d_in[3];
    const float* mean  = (const float*)d_in[4];
    const float* var   = (const float*)d_in[5];
    const float* wh    = (const float*)d_in[6];
    const float* ww    = (const float*)d_in[7];
    float* out = (float*)d_out;

    k1_stats<<<B_ * C_, 256>>>(x);
    k2_fused<<<B_,       512>>>(w1, gamma, beta, mean, var, wh, ww);
    k3_apply<<<B_ * C_,  256>>>(x, out);
}

// round 6
// speedup vs baseline: 2.2564x; 1.0537x over previous
#include <cuda_runtime.h>
#include <cuda_bf16.h>
#include <math.h>

// Problem constants
#define B_   32
#define C_   256
#define H_   64
#define W_   64
#define MIP_ 8
#define OUP_ 256

// Scratch (device globals — no allocation allowed)
__device__ __align__(16) float g_a [B_ * C_ * (H_ + W_)];   // 4 MiB  (a_h | a_w per plane)
__device__ __align__(16) float g_y [B_ * MIP_ * 128];       // y after BN+hswish (128 KB)
__device__ __align__(16) float g_gh[B_ * OUP_ * H_];        // 2 MiB
__device__ __align__(16) float g_gw[B_ * OUP_ * W_];        // 2 MiB

// ---------------------------------------------------------------------------
// K1: per-(b,c) plane stats -> a[plane][0..127]. TWO planes per CTA:
// 8 front-batched LDG.128 per thread (MLP_p1=8), reduce phases amortized,
// softmax/emit tail uses 4 warps (plane x kind).
//   a_h[h] = (rowsum[h] + softmax_h(rowmax)[h]) / 64
//   a_w[w] = (colsum[w] + softmax_w(colmax)[w]) / 64
// ---------------------------------------------------------------------------
__global__ __launch_bounds__(256) void k1_stats(const float* __restrict__ x)
{
    __shared__ float rmax[2][64], rsum[2][64], cmax[2][64], csum[2][64];
    __shared__ float pmax[16][68], psum[16][68];   // pitch 68: conflict-free f4 stores

    const int tid = threadIdx.x;
    const long p0 = (long)blockIdx.x * 2;          // first plane of this CTA
    const float4* xp = reinterpret_cast<const float4*>(x) + p0 * 1024;

    float4 v[8];                                   // v[0..3] plane0, v[4..7] plane1
    #pragma unroll
    for (int i = 0; i < 8; i++) v[i] = xp[i * 256 + tid];

    #pragma unroll
    for (int pl = 0; pl < 2; pl++) {
        // Row reductions: 16 consecutive lanes cover one full row per i
        #pragma unroll
        for (int i = 0; i < 4; i++) {
            const float4 q = v[pl * 4 + i];
            float mx = fmaxf(fmaxf(q.x, q.y), fmaxf(q.z, q.w));
            float sm = (q.x + q.y) + (q.z + q.w);
            #pragma unroll
            for (int o = 1; o < 16; o <<= 1) {
                mx = fmaxf(mx, __shfl_xor_sync(0xFFFFFFFFu, mx, o));
                sm += __shfl_xor_sync(0xFFFFFFFFu, sm, o);
            }
            if ((tid & 15) == 0) {
                int r = i * 16 + (tid >> 4);
                rmax[pl][r] = mx; rsum[pl][r] = sm;
            }
        }

        // Column partials: thread owns cols 4k..4k+3 (k = tid&15) over its 4 rows
        float4 a0 = v[pl * 4], a1 = v[pl * 4 + 1], a2 = v[pl * 4 + 2], a3 = v[pl * 4 + 3];
        float cm0 = fmaxf(fmaxf(a0.x, a1.x), fmaxf(a2.x, a3.x));
        float cm1 = fmaxf(fmaxf(a0.y, a1.y), fmaxf(a2.y, a3.y));
        float cm2 = fmaxf(fmaxf(a0.z, a1.z), fmaxf(a2.z, a3.z));
        float cm3 = fmaxf(fmaxf(a0.w, a1.w), fmaxf(a2.w, a3.w));
        float cs0 = (a0.x + a1.x) + (a2.x + a3.x);
        float cs1 = (a0.y + a1.y) + (a2.y + a3.y);
        float cs2 = (a0.z + a1.z) + (a2.z + a3.z);
        float cs3 = (a0.w + a1.w) + (a2.w + a3.w);
        {
            int g = tid >> 4, k = tid & 15;
            *reinterpret_cast<float4*>(&pmax[g][k * 4]) = make_float4(cm0, cm1, cm2, cm3);
            *reinterpret_cast<float4*>(&psum[g][k * 4]) = make_float4(cs0, cs1, cs2, cs3);
        }
        __syncthreads();

        if (tid < 64) {
            float m = pmax[0][tid], s = psum[0][tid];
            #pragma unroll
            for (int g = 1; g < 16; g++) { m = fmaxf(m, pmax[g][tid]); s += psum[g][tid]; }
            cmax[pl][tid] = m; csum[pl][tid] = s;
        }
        __syncthreads();                            // pmax/psum reused by next plane
    }

    // Softmax + emit: warp = (pl, kind). kind 0 -> rows (a_h), 1 -> cols (a_w)
    const int w    = tid >> 5;
    const int lane = tid & 31;
    if (w < 4) {
        const int pl   = w >> 1;
        const int kind = w & 1;
        const float* ma = (kind == 0) ? rmax[pl] : cmax[pl];
        const float* sa = (kind == 0) ? rsum[pl] : csum[pl];
        float v0 = ma[lane], v1 = ma[lane + 32];
        float m = fmaxf(v0, v1);
        #pragma unroll
        for (int o = 16; o > 0; o >>= 1) m = fmaxf(m, __shfl_xor_sync(0xFFFFFFFFu, m, o));
        float e0 = __expf(v0 - m), e1 = __expf(v1 - m);
        float s = e0 + e1;
        #pragma unroll
        for (int o = 16; o > 0; o >>= 1) s += __shfl_xor_sync(0xFFFFFFFFu, s, o);
        float inv = 1.f / s;
        float* ob = g_a + (p0 + pl) * 128 + kind * 64;
        ob[lane]      = (sa[lane]      + e0 * inv) * 0.015625f;   // /64
        ob[lane + 32] = (sa[lane + 32] + e1 * inv) * 0.015625f;
    }
}

// ---------------------------------------------------------------------------
// K2a: per batch b — y = hswish(BN(w1 @ a)) -> g_y[b][m][128]
//   phase1: 8 warps, warp = 32-c slice, lane = s4 (float4 of s), MLP~8
//   phase2: reduce 8 partials + BN + hswish, coalesced f4 store to g_y
// ---------------------------------------------------------------------------
__global__ __launch_bounds__(256) void k2a_y(const float* __restrict__ w1,
                                             const float* __restrict__ gamma,
                                             const float* __restrict__ beta,
                                             const float* __restrict__ mean,
                                             const float* __restrict__ var)
{
    __shared__ float w1s[MIP_ * C_];       // 8 KB
    __shared__ float part[8 * 32 * 33];    // [cgrp][lane(s4)][33]  ~33 KB, pitch 33

    const int tid = threadIdx.x;
    const int b   = blockIdx.x;

    for (int i = tid; i < MIP_ * C_; i += 256) w1s[i] = w1[i];
    __syncthreads();

    // -------- phase 1
    {
        const int wrp  = tid >> 5;         // cgrp 0..7
        const int lane = tid & 31;         // s4 0..31
        const float4* ap = reinterpret_cast<const float4*>(g_a) +
                           ((long)b * C_ + wrp * 32) * 32 + lane;

        float acc[MIP_][4];
        #pragma unroll
        for (int m = 0; m < MIP_; m++)
            #pragma unroll
            for (int j = 0; j < 4; j++) acc[m][j] = 0.f;

        #pragma unroll 4
        for (int k = 0; k < 32; k++) {
            float4 av = ap[k * 32];                     // a[b][c][s4*4..]
            const float* wc = &w1s[wrp * 32 + k];       // w1[m][c], broadcast
            #pragma unroll
            for (int m = 0; m < MIP_; m++) {
                float wv = wc[m * C_];
                acc[m][0] = fmaf(wv, av.x, acc[m][0]);
                acc[m][1] = fmaf(wv, av.y, acc[m][1]);
                acc[m][2] = fmaf(wv, av.z, acc[m][2]);
                acc[m][3] = fmaf(wv, av.w, acc[m][3]);
            }
        }
        float* pb = &part[(wrp * 32 + lane) * 33];
        #pragma unroll
        for (int m = 0; m < MIP_; m++)
            #pragma unroll
            for (int j = 0; j < 4; j++) pb[m * 4 + j] = acc[m][j];
    }
    __syncthreads();

    // -------- phase 2: reduce c-groups, BN + hswish, coalesced store to g_y
    {
        const int m  = tid >> 5;
        const int s4 = tid & 31;
        const float sc = gamma[m] * rsqrtf(var[m] + 1e-5f);
        const float sf = beta[m] - mean[m] * sc;
        float r[4];
        #pragma unroll
        for (int j = 0; j < 4; j++) {
            float s = 0.f;
            #pragma unroll
            for (int g = 0; g < 8; g++) s += part[(g * 32 + s4) * 33 + m * 4 + j];
            float v = fmaf(s, sc, sf);
            r[j] = v * fminf(fmaxf(v + 3.f, 0.f), 6.f) * (1.f / 6.f);   // hswish
        }
        *reinterpret_cast<float4*>(&g_y[(b * MIP_ + m) * 128 + s4 * 4]) =
            make_float4(r[0], r[1], r[2], r[3]);
    }
}

// ---------------------------------------------------------------------------
// K2b: gates. grid = B_*16 blocks x 256 threads.
// Thread -> (b, o, kind in {gh,gw}, 8-wide h segment): 8 outputs each.
// ---------------------------------------------------------------------------
__global__ __launch_bounds__(256) void k2b_gate(const float* __restrict__ wh,
                                                const float* __restrict__ ww)
{
    __shared__ float ys[MIP_ * 128];          // y for this batch (4 KB)

    const int tid = threadIdx.x;
    const int b   = blockIdx.x >> 4;          // 16 blocks per batch

    for (int i = tid; i < MIP_ * 128; i += 256) ys[i] = g_y[b * (MIP_ * 128) + i];
    __syncthreads();

    const int gidx = blockIdx.x * 256 + tid;
    const int bo   = gidx >> 4;               // b*256 + o
    const int o    = bo & 255;
    const int kind = (gidx >> 3) & 1;         // 0 -> gh, 1 -> gw
    const int seg  = gidx & 7;                // h chunk of 8
    const int base = kind * 64 + seg * 8;

    const float* wrow = (kind ? ww : wh) + o * MIP_;
    const float4 w0 = *reinterpret_cast<const float4*>(wrow);
    const float4 w1v = *reinterpret_cast<const float4*>(wrow + 4);
    float wr[MIP_] = {w0.x, w0.y, w0.z, w0.w, w1v.x, w1v.y, w1v.z, w1v.w};

    float acc[8];
    #pragma unroll
    for (int j = 0; j < 8; j++) acc[j] = 0.f;

    #pragma unroll
    for (int m = 0; m < MIP_; m++) {
        float4 y0 = *reinterpret_cast<const float4*>(&ys[m * 128 + base]);
        float4 y1 = *reinterpret_cast<const float4*>(&ys[m * 128 + base + 4]);
        acc[0] = fmaf(wr[m], y0.x, acc[0]);
        acc[1] = fmaf(wr[m], y0.y, acc[1]);
        acc[2] = fmaf(wr[m], y0.z, acc[2]);
        acc[3] = fmaf(wr[m], y0.w, acc[3]);
        acc[4] = fmaf(wr[m], y1.x, acc[4]);
        acc[5] = fmaf(wr[m], y1.y, acc[5]);
        acc[6] = fmaf(wr[m], y1.z, acc[6]);
        acc[7] = fmaf(wr[m], y1.w, acc[7]);
    }

    float r[8];
    #pragma unroll
    for (int j = 0; j < 8; j++) r[j] = __fdividef(1.f, 1.f + __expf(-acc[j]));

    float* outp = (kind ? g_gw : g_gh) + bo * 64 + seg * 8;
    *reinterpret_cast<float4*>(outp)     = make_float4(r[0], r[1], r[2], r[3]);
    *reinterpret_cast<float4*>(outp + 4) = make_float4(r[4], r[5], r[6], r[7]);
}

// ---------------------------------------------------------------------------
// K3: out = x * g_h[bc,h] * g_w[bc,w]. One block == one (b,c) plane.
// 4 front-batched streaming loads per thread; gw hoisted (constant over k).
// Reverse block order reuses the x tail K1 left in L2.
// ---------------------------------------------------------------------------
__global__ __launch_bounds__(256) void k3_apply(const float* __restrict__ x,
                                                float* __restrict__ out)
{
    const int  bc   = gridDim.x - 1 - blockIdx.x;       // plane index
    const int  tid  = threadIdx.x;
    const long base = (long)bc * 1024 + tid;            // float4 index

    const float4* xp = reinterpret_cast<const float4*>(x);
    float4*       op = reinterpret_cast<float4*>(out);

    float4 xv[4];
    #pragma unroll
    for (int k = 0; k < 4; k++) xv[k] = __ldcs(xp + base + k * 256);

    const float4 gwv = *(reinterpret_cast<const float4*>(g_gw) + bc * 16 + (tid & 15));
    const float* ghp = g_gh + bc * 64;

    #pragma unroll
    for (int k = 0; k < 4; k++) {
        float ghv = ghp[k * 16 + (tid >> 4)];
        float4 ov;
        ov.x = xv[k].x * ghv * gwv.x;
        ov.y = xv[k].y * ghv * gwv.y;
        ov.z = xv[k].z * ghv * gwv.z;
        ov.w = xv[k].w * ghv * gwv.w;
        __stcs(op + base + k * 256, ov);
    }
}

// ---------------------------------------------------------------------------
extern "C" void kernel_launch(void* const* d_in, const int* in_sizes, int n_in,
                              void* d_out, int out_size)
{
    const float* x     = (const float*)d_in[0];
    const float* w1    = (const float*)d_in[1];
    const float* gamma = (const float*)d_in[2];
    const float* beta  = (const float*)d_in[3];
    const float* mean  = (const float*)d_in[4];
    const float* var   = (const float*)d_in[5];
    const float* wh    = (const float*)d_in[6];
    const float* ww    = (const float*)d_in[7];
    float* out = (float*)d_out;

    k1_stats<<<B_ * C_ / 2, 256>>>(x);
    k2a_y   <<<B_,          256>>>(w1, gamma, beta, mean, var);
    k2b_gate<<<B_ * 16,     256>>>(wh, ww);
    k3_apply<<<B_ * C_,     256>>>(x, out);
}